// round 1
// baseline (speedup 1.0000x reference)
#include <cuda_runtime.h>
#include <cstdint>

#define BB 64
#define SS 512
#define HH 768
#define EE 512
#define TT 256

// Scratch for pooled output [B, T, H] (allocation-free rule: __device__ global)
__device__ float g_pooled[(size_t)BB * TT * HH];

// ---------------------------------------------------------------------------
// Kernel 1: segment-mean pooling.
// word_ids[b,:] is sorted, so segment t is the contiguous range found by
// binary search. One block per (b, t); 192 threads, one float4 each (H=768).
// ---------------------------------------------------------------------------
__global__ __launch_bounds__(192) void pool_kernel(
        const float* __restrict__ hs,   // [B, S, H]
        const int*   __restrict__ wid,  // [B, S]
        const int*   __restrict__ tlen) // [B]
{
    const int t   = blockIdx.x;
    const int b   = blockIdx.y;
    const int tid = threadIdx.x;

    const int* w = wid + b * SS;
    // lower_bound(t)
    int l = 0, r = SS;
    while (l < r) { int m = (l + r) >> 1; if (w[m] < t) l = m + 1; else r = m; }
    const int lo = l;
    // upper_bound(t)
    r = SS;
    while (l < r) { int m = (l + r) >> 1; if (w[m] <= t) l = m + 1; else r = m; }
    const int hi = l;

    const bool valid = (t < tlen[b]) && (hi > lo);
    const float inv = valid ? (1.0f / (float)(hi - lo)) : 0.0f;

    float4 acc = make_float4(0.f, 0.f, 0.f, 0.f);
    if (valid) {
        const float* p = hs + ((size_t)b * SS + lo) * HH + tid * 4;
        for (int i = lo; i < hi; ++i, p += HH) {
            float4 v = *(const float4*)p;
            acc.x += v.x; acc.y += v.y; acc.z += v.z; acc.w += v.w;
        }
    }
    acc.x *= inv; acc.y *= inv; acc.z *= inv; acc.w *= inv;
    float* outp = g_pooled + ((size_t)b * TT + t) * HH + tid * 4;
    *(float4*)outp = acc;
}

// ---------------------------------------------------------------------------
// Kernel 2: out[m, e] = pooled[m, :] . W[e, :] + bias[e]
// M = B*T = 16384, N = E = 512, K = H = 768.
// TF32 tensor-core GEMM: mma.sync.m16n8k8.row.col.f32.tf32.tf32.f32
// Block tile 128x64, BK=16, 8 warps (4m x 2n), warp tile 32x32.
// Tiles fully past token_lengths[b] write bias only (pooled rows are zero
// for partially-masked tiles, so bias-add is automatically correct there).
// ---------------------------------------------------------------------------
#define BM 128
#define BN 64
#define BK 16

__device__ __forceinline__ unsigned f2tf32(float x) {
    unsigned u;
    asm("cvt.rna.tf32.f32 %0, %1;" : "=r"(u) : "f"(x));
    return u;
}

__global__ __launch_bounds__(256) void gemm_tf32_kernel(
        const float* __restrict__ Wm,   // [E, H]
        const float* __restrict__ bias, // [E]
        const int*   __restrict__ tlen, // [B]
        float*       __restrict__ out)  // [M, E]
{
    const int tid = threadIdx.x;
    const int n0  = blockIdx.x * BN;
    const int m0  = blockIdx.y * BM;
    const int batch = m0 / TT;
    const int t0    = m0 % TT;

    float* cbase = out + (size_t)m0 * EE + n0;

    if (t0 >= tlen[batch]) {
        // fully masked tile: output = bias broadcast
        #pragma unroll 4
        for (int i = tid; i < BM * (BN / 4); i += 256) {
            int r = i >> 4;            // BN/4 = 16
            int c = (i & 15) * 4;
            float4 bv = *(const float4*)(bias + n0 + c);
            *(float4*)(cbase + (size_t)r * EE + c) = bv;
        }
        return;
    }

    // Shared staging in tf32 bit patterns, [k][mn] layout.
    // Strides chosen so stride % 32 == 8 -> fragment loads (8*tg + g) are
    // bank-conflict-free; loaders are lane-contiguous in m/n so stores are too.
    __shared__ unsigned As[BK][BM + 8];   // stride 136
    __shared__ unsigned Bs[BK][BN + 8];   // stride 72

    const float* Ag = g_pooled + (size_t)m0 * HH;
    const float* Bg = Wm + (size_t)n0 * HH;

    // A loader: 128 rows x 16 k = 2048 floats; tid -> m = tid&127, k-half = (tid>>7)*8
    const int am = tid & 127;
    const int ak = (tid >> 7) * 8;
    // B loader: 64 rows x 16 k = 1024 floats; tid -> n = tid&63, k-quarter = (tid>>6)*4
    const int bn_ = tid & 63;
    const int bk  = (tid >> 6) * 4;

    const int wid  = tid >> 5;
    const int lane = tid & 31;
    const int wm = wid >> 1;      // 0..3 : warp row
    const int wn = wid & 1;       // 0..1 : warp col
    const int g  = lane >> 2;     // groupID 0..7
    const int tg = lane & 3;      // threadInGroup 0..3

    float acc[2][4][4];
    #pragma unroll
    for (int i = 0; i < 2; ++i)
        #pragma unroll
        for (int j = 0; j < 4; ++j)
            #pragma unroll
            for (int q = 0; q < 4; ++q) acc[i][j][q] = 0.0f;

    for (int k0 = 0; k0 < HH; k0 += BK) {
        float4 av0 = *(const float4*)(Ag + (size_t)am * HH + k0 + ak);
        float4 av1 = *(const float4*)(Ag + (size_t)am * HH + k0 + ak + 4);
        float4 bv  = *(const float4*)(Bg + (size_t)bn_ * HH + k0 + bk);

        As[ak + 0][am] = f2tf32(av0.x); As[ak + 1][am] = f2tf32(av0.y);
        As[ak + 2][am] = f2tf32(av0.z); As[ak + 3][am] = f2tf32(av0.w);
        As[ak + 4][am] = f2tf32(av1.x); As[ak + 5][am] = f2tf32(av1.y);
        As[ak + 6][am] = f2tf32(av1.z); As[ak + 7][am] = f2tf32(av1.w);
        Bs[bk + 0][bn_] = f2tf32(bv.x); Bs[bk + 1][bn_] = f2tf32(bv.y);
        Bs[bk + 2][bn_] = f2tf32(bv.z); Bs[bk + 3][bn_] = f2tf32(bv.w);
        __syncthreads();

        #pragma unroll
        for (int ks = 0; ks < 2; ++ks) {
            const int kb = ks * 8;
            unsigned afrag[2][4];
            unsigned bfrag[4][2];
            #pragma unroll
            for (int i = 0; i < 2; ++i) {
                const int mrow = wm * 32 + i * 16;
                afrag[i][0] = As[kb + tg    ][mrow + g];
                afrag[i][1] = As[kb + tg    ][mrow + g + 8];
                afrag[i][2] = As[kb + tg + 4][mrow + g];
                afrag[i][3] = As[kb + tg + 4][mrow + g + 8];
            }
            #pragma unroll
            for (int j = 0; j < 4; ++j) {
                const int ncol = wn * 32 + j * 8;
                bfrag[j][0] = Bs[kb + tg    ][ncol + g];
                bfrag[j][1] = Bs[kb + tg + 4][ncol + g];
            }
            #pragma unroll
            for (int i = 0; i < 2; ++i)
                #pragma unroll
                for (int j = 0; j < 4; ++j) {
                    asm volatile(
                        "mma.sync.aligned.m16n8k8.row.col.f32.tf32.tf32.f32 "
                        "{%0,%1,%2,%3}, {%4,%5,%6,%7}, {%8,%9}, {%0,%1,%2,%3};"
                        : "+f"(acc[i][j][0]), "+f"(acc[i][j][1]),
                          "+f"(acc[i][j][2]), "+f"(acc[i][j][3])
                        : "r"(afrag[i][0]), "r"(afrag[i][1]),
                          "r"(afrag[i][2]), "r"(afrag[i][3]),
                          "r"(bfrag[j][0]), "r"(bfrag[j][1]));
                }
        }
        __syncthreads();
    }

    // Epilogue: C fragment (g, 2tg) / (g+8, 2tg) pairs, add bias, float2 stores.
    #pragma unroll
    for (int i = 0; i < 2; ++i) {
        const int mrow = wm * 32 + i * 16;
        #pragma unroll
        for (int j = 0; j < 4; ++j) {
            const int ncol = wn * 32 + j * 8;
            const float bv0 = bias[n0 + ncol + 2 * tg];
            const float bv1 = bias[n0 + ncol + 2 * tg + 1];
            float2 v0 = make_float2(acc[i][j][0] + bv0, acc[i][j][1] + bv1);
            float2 v1 = make_float2(acc[i][j][2] + bv0, acc[i][j][3] + bv1);
            *(float2*)(cbase + (size_t)(mrow + g    ) * EE + ncol + 2 * tg) = v0;
            *(float2*)(cbase + (size_t)(mrow + g + 8) * EE + ncol + 2 * tg) = v1;
        }
    }
}

// ---------------------------------------------------------------------------
extern "C" void kernel_launch(void* const* d_in, const int* in_sizes, int n_in,
                              void* d_out, int out_size) {
    const float* hs   = (const float*)d_in[0];  // [64, 512, 768]
    const int*   wid  = (const int*)  d_in[1];  // [64, 512]
    const int*   tlen = (const int*)  d_in[2];  // [64]
    const float* Wm   = (const float*)d_in[3];  // [512, 768]
    const float* bias = (const float*)d_in[4];  // [512]
    float*       out  = (float*)d_out;          // [64, 256, 512]

    pool_kernel<<<dim3(TT, BB), 192>>>(hs, wid, tlen);
    gemm_tf32_kernel<<<dim3(EE / BN, (BB * TT) / BM), 256>>>(Wm, bias, tlen, out);
}